// round 1
// baseline (speedup 1.0000x reference)
#include <cuda_runtime.h>
#include <cuda_bf16.h>

// AdditiveAttention: out[b,q,d] = softmax_k( sum_h w_v[h]*tanh(qp[b,q,h]+kp[b,k,h]) ) @ values
// qp = queries @ W_q^T, kp = keys @ W_k^T
// B=4, Q=K=512, H=256. All fp32.

#define Bv 4
#define Qv 512
#define Kv 512
#define Hv 256
#define MROWS (Bv * Qv)          // 2048

// Scratch for projected q/k (device globals: no allocation allowed)
__device__ float g_qp[MROWS * Hv];
__device__ float g_kp[MROWS * Hv];

__device__ __forceinline__ float tanh_ap(float x) {
    float y;
    asm("tanh.approx.f32 %0, %1;" : "=f"(y) : "f"(x));
    return y;
}
__device__ __forceinline__ float ex2_ap(float x) {
    float y;
    asm("ex2.approx.f32 %0, %1;" : "=f"(y) : "f"(x));
    return y;
}

// ---------------------------------------------------------------------------
// Projection GEMM: C[m,o] = sum_h A[m,h] * W[o,h]   (A: 2048x256, W: 256x256)
// Block tile 64x64, K-chunk 16, 256 threads, 4x4 per-thread microtile.
// blockIdx.z selects (queries,W_q)->g_qp vs (keys,W_k)->g_kp.
// ---------------------------------------------------------------------------
__global__ __launch_bounds__(256) void proj_kernel(
    const float* __restrict__ A0, const float* __restrict__ W0, float* __restrict__ C0,
    const float* __restrict__ A1, const float* __restrict__ W1, float* __restrict__ C1)
{
    const float* A; const float* W; float* C;
    if (blockIdx.z == 0) { A = A0; W = W0; C = C0; }
    else                 { A = A1; W = W1; C = C1; }

    __shared__ float As[16 * 68];   // [k][m], padded stride 68
    __shared__ float Ws[16 * 68];   // [k][n]

    const int tid = threadIdx.x;
    const int bm = blockIdx.y * 64;
    const int bn = blockIdx.x * 64;
    const int lr = tid >> 2;            // load row 0..63
    const int lc = (tid & 3) << 2;      // load col4 0,4,8,12
    const int tm = (tid >> 4) << 2;     // 0..60
    const int tn = (tid & 15) << 2;     // 0..60

    float acc[4][4];
#pragma unroll
    for (int i = 0; i < 4; i++)
#pragma unroll
        for (int j = 0; j < 4; j++) acc[i][j] = 0.f;

    for (int k0 = 0; k0 < Hv; k0 += 16) {
        float4 a = *(const float4*)&A[(bm + lr) * Hv + k0 + lc];
        float4 w = *(const float4*)&W[(bn + lr) * Hv + k0 + lc];
        As[(lc + 0) * 68 + lr] = a.x;
        As[(lc + 1) * 68 + lr] = a.y;
        As[(lc + 2) * 68 + lr] = a.z;
        As[(lc + 3) * 68 + lr] = a.w;
        Ws[(lc + 0) * 68 + lr] = w.x;
        Ws[(lc + 1) * 68 + lr] = w.y;
        Ws[(lc + 2) * 68 + lr] = w.z;
        Ws[(lc + 3) * 68 + lr] = w.w;
        __syncthreads();
#pragma unroll
        for (int k = 0; k < 16; k++) {
            float4 av = *(const float4*)&As[k * 68 + tm];
            float4 wv = *(const float4*)&Ws[k * 68 + tn];
            float ar[4] = {av.x, av.y, av.z, av.w};
            float wr[4] = {wv.x, wv.y, wv.z, wv.w};
#pragma unroll
            for (int i = 0; i < 4; i++)
#pragma unroll
                for (int j = 0; j < 4; j++) acc[i][j] = fmaf(ar[i], wr[j], acc[i][j]);
        }
        __syncthreads();
    }
#pragma unroll
    for (int i = 0; i < 4; i++) {
        float4 r = make_float4(acc[i][0], acc[i][1], acc[i][2], acc[i][3]);
        *(float4*)&C[(bm + tm + i) * Hv + bn + tn] = r;
    }
}

// ---------------------------------------------------------------------------
// Fused: scores (tanh) + softmax + P@V.
// Grid: 256 blocks; block handles TQ=8 queries of one batch. 256 threads = 8 warps,
// warp w owns query w. Phase 1: key tiles of 32 (lane <-> key), XOR-swizzled smem
// for conflict-free float4 reads along h. Per-lane private score accumulator.
// ---------------------------------------------------------------------------
#define TQ 8
#define TK 32
// smem floats: qs 2048 | wv 256 | kb 8192 | ps 4096  = 14592 floats = 58368 B
#define SM_QS   0
#define SM_WV   2048
#define SM_KB   2304
#define SM_PS   (2304 + 8192)
#define SM_FLOATS 14592

__global__ __launch_bounds__(256) void fused_kernel(
    const float* __restrict__ qp, const float* __restrict__ kp,
    const float* __restrict__ V, const float* __restrict__ wv_g,
    float* __restrict__ out)
{
    extern __shared__ float sm[];
    float* qs = sm + SM_QS;
    float* wv = sm + SM_WV;
    float* kb = sm + SM_KB;
    float* ps = sm + SM_PS;

    const int tid  = threadIdx.x;
    const int lane = tid & 31;
    const int q    = tid >> 5;                 // warp id = query index in tile
    const int bi   = blockIdx.x;
    const int b    = bi >> 6;                  // 64 blocks per batch
    const int qbase = (bi & 63) * TQ;

    // Load q-tile [8][256] and w_v[256]
#pragma unroll
    for (int i = tid; i < TQ * 64; i += 256) {
        int r = i >> 6, c4 = (i & 63) << 2;
        *(float4*)&qs[r * Hv + c4] =
            *(const float4*)&qp[(size_t)((b * Qv + qbase + r) * Hv) + c4];
    }
    if (tid < 64) *(float4*)&wv[tid * 4] = *(const float4*)&wv_g[tid * 4];
    __syncthreads();

    // ---------------- Phase 1: scores ----------------
    for (int kt = 0; kt < Kv; kt += TK) {
        // load kp tile [32][256] with XOR swizzle on float4 column
#pragma unroll
        for (int j = 0; j < 8; j++) {
            int idx = j * 256 + tid;
            int r = idx >> 6;           // key row 0..31
            int c = idx & 63;           // float4 col 0..63
            float4 v = *(const float4*)&kp[(size_t)((b * Kv + kt + r) * Hv) + (c << 2)];
            *(float4*)&kb[(r * 64 + (c ^ r)) * 4] = v;
        }
        __syncthreads();

        // lane owns key kt+lane; accumulate over all 256 h
        float acc0 = 0.f, acc1 = 0.f;
#pragma unroll 8
        for (int h4 = 0; h4 < 64; ++h4) {
            float4 qv = *(const float4*)&qs[q * Hv + h4 * 4];       // broadcast
            float4 wvv = *(const float4*)&wv[h4 * 4];               // broadcast
            float4 kv = *(const float4*)&kb[(lane * 64 + (h4 ^ lane)) * 4];
            acc0 = fmaf(wvv.x, tanh_ap(qv.x + kv.x), acc0);
            acc1 = fmaf(wvv.y, tanh_ap(qv.y + kv.y), acc1);
            acc0 = fmaf(wvv.z, tanh_ap(qv.z + kv.z), acc0);
            acc1 = fmaf(wvv.w, tanh_ap(qv.w + kv.w), acc1);
        }
        ps[q * Kv + kt + lane] = acc0 + acc1;
        __syncthreads();
    }

    // ---------------- Softmax (per warp over its 512 scores) ----------------
    {
        const float LOG2E = 1.4426950408889634f;
        float4 xv[4];
        float mx = -1e30f;
#pragma unroll
        for (int j = 0; j < 4; j++) {
            xv[j] = *(const float4*)&ps[q * Kv + j * 128 + lane * 4];
            mx = fmaxf(mx, fmaxf(fmaxf(xv[j].x, xv[j].y), fmaxf(xv[j].z, xv[j].w)));
        }
#pragma unroll
        for (int off = 16; off > 0; off >>= 1)
            mx = fmaxf(mx, __shfl_xor_sync(0xffffffffu, mx, off));
        float s = 0.f;
#pragma unroll
        for (int j = 0; j < 4; j++) {
            xv[j].x = ex2_ap((xv[j].x - mx) * LOG2E);
            xv[j].y = ex2_ap((xv[j].y - mx) * LOG2E);
            xv[j].z = ex2_ap((xv[j].z - mx) * LOG2E);
            xv[j].w = ex2_ap((xv[j].w - mx) * LOG2E);
            s += xv[j].x + xv[j].y + xv[j].z + xv[j].w;
        }
#pragma unroll
        for (int off = 16; off > 0; off >>= 1)
            s += __shfl_xor_sync(0xffffffffu, s, off);
        float inv = __fdividef(1.f, s);
#pragma unroll
        for (int j = 0; j < 4; j++) {
            xv[j].x *= inv; xv[j].y *= inv; xv[j].z *= inv; xv[j].w *= inv;
            *(float4*)&ps[q * Kv + j * 128 + lane * 4] = xv[j];
        }
    }

    // ---------------- Phase 2: out = P @ V ----------------
    float4 o0 = make_float4(0.f, 0.f, 0.f, 0.f);
    float4 o1 = make_float4(0.f, 0.f, 0.f, 0.f);
    for (int kt = 0; kt < Kv; kt += TK) {
        // load V tile [32][256] plain layout
#pragma unroll
        for (int j = 0; j < 8; j++) {
            int idx = j * 256 + tid;
            int r = idx >> 6;
            int c = idx & 63;
            *(float4*)&kb[r * Hv + c * 4] =
                *(const float4*)&V[(size_t)((b * Kv + kt + r) * Hv) + c * 4];
        }
        __syncthreads();
#pragma unroll 8
        for (int kk = 0; kk < TK; ++kk) {
            float p = ps[q * Kv + kt + kk];                      // broadcast
            float4 v0 = *(const float4*)&kb[kk * Hv + lane * 4];
            float4 v1 = *(const float4*)&kb[kk * Hv + 128 + lane * 4];
            o0.x = fmaf(p, v0.x, o0.x); o0.y = fmaf(p, v0.y, o0.y);
            o0.z = fmaf(p, v0.z, o0.z); o0.w = fmaf(p, v0.w, o0.w);
            o1.x = fmaf(p, v1.x, o1.x); o1.y = fmaf(p, v1.y, o1.y);
            o1.z = fmaf(p, v1.z, o1.z); o1.w = fmaf(p, v1.w, o1.w);
        }
        __syncthreads();
    }
    size_t obase = (size_t)((b * Qv + qbase + q) * Hv) + lane * 4;
    *(float4*)&out[obase]       = o0;
    *(float4*)&out[obase + 128] = o1;
}

extern "C" void kernel_launch(void* const* d_in, const int* in_sizes, int n_in,
                              void* d_out, int out_size)
{
    const float* queries = (const float*)d_in[0];
    const float* keys    = (const float*)d_in[1];
    const float* values  = (const float*)d_in[2];
    const float* W_q     = (const float*)d_in[3];
    const float* W_k     = (const float*)d_in[4];
    const float* w_v     = (const float*)d_in[5];
    float* out = (float*)d_out;

    float *qp, *kp;
    cudaGetSymbolAddress((void**)&qp, g_qp);
    cudaGetSymbolAddress((void**)&kp, g_kp);

    // Both projections in one launch (grid.z selects operand set)
    proj_kernel<<<dim3(4, 32, 2), 256>>>(queries, W_q, qp, keys, W_k, kp);

    const int smem_bytes = SM_FLOATS * (int)sizeof(float);   // 58368
    cudaFuncSetAttribute(fused_kernel, cudaFuncAttributeMaxDynamicSharedMemorySize, smem_bytes);
    fused_kernel<<<256, 256, smem_bytes>>>(qp, kp, values, w_v, out);
}

// round 2
// speedup vs baseline: 1.1525x; 1.1525x over previous
#include <cuda_runtime.h>
#include <cuda_fp16.h>

// AdditiveAttention: out = softmax_k( sum_h w_v[h]*tanh(qp[q,h]+kp[k,h]) ) @ V
// B=4, Q=K=512, H=256, fp32 in/out.
// Pipeline: proj (f32 GEMM) -> score (f16x2 tanh) -> softmax+PV (f32).

#define Bv 4
#define Qv 512
#define Kv 512
#define Hv 256
#define MROWS (Bv * Qv)          // 2048

__device__ float g_qp[MROWS * Hv];
__device__ float g_kp[MROWS * Hv];
__device__ float g_sc[Bv * Qv * Kv];      // scores, 4MB

__device__ __forceinline__ __half2 tanh2_ap(__half2 x) {
    unsigned xi = *(unsigned*)&x, yi;
    asm("tanh.approx.f16x2 %0, %1;" : "=r"(yi) : "r"(xi));
    return *(__half2*)&yi;
}
__device__ __forceinline__ float ex2_ap(float x) {
    float y;
    asm("ex2.approx.f32 %0, %1;" : "=f"(y) : "f"(x));
    return y;
}

// ---------------------------------------------------------------------------
// Projection GEMM: C[m,o] = sum_h A[m,h] * W[o,h]  (2048x256 @ 256x256^T)
// ---------------------------------------------------------------------------
__global__ __launch_bounds__(256) void proj_kernel(
    const float* __restrict__ A0, const float* __restrict__ W0, float* __restrict__ C0,
    const float* __restrict__ A1, const float* __restrict__ W1, float* __restrict__ C1)
{
    const float* A; const float* W; float* C;
    if (blockIdx.z == 0) { A = A0; W = W0; C = C0; }
    else                 { A = A1; W = W1; C = C1; }

    __shared__ float As[16 * 68];
    __shared__ float Ws[16 * 68];

    const int tid = threadIdx.x;
    const int bm = blockIdx.y * 64;
    const int bn = blockIdx.x * 64;
    const int lr = tid >> 2;
    const int lc = (tid & 3) << 2;
    const int tm = (tid >> 4) << 2;
    const int tn = (tid & 15) << 2;

    float acc[4][4];
#pragma unroll
    for (int i = 0; i < 4; i++)
#pragma unroll
        for (int j = 0; j < 4; j++) acc[i][j] = 0.f;

    for (int k0 = 0; k0 < Hv; k0 += 16) {
        float4 a = *(const float4*)&A[(bm + lr) * Hv + k0 + lc];
        float4 w = *(const float4*)&W[(bn + lr) * Hv + k0 + lc];
        As[(lc + 0) * 68 + lr] = a.x; As[(lc + 1) * 68 + lr] = a.y;
        As[(lc + 2) * 68 + lr] = a.z; As[(lc + 3) * 68 + lr] = a.w;
        Ws[(lc + 0) * 68 + lr] = w.x; Ws[(lc + 1) * 68 + lr] = w.y;
        Ws[(lc + 2) * 68 + lr] = w.z; Ws[(lc + 3) * 68 + lr] = w.w;
        __syncthreads();
#pragma unroll
        for (int k = 0; k < 16; k++) {
            float4 av = *(const float4*)&As[k * 68 + tm];
            float4 wv = *(const float4*)&Ws[k * 68 + tn];
            float ar[4] = {av.x, av.y, av.z, av.w};
            float wr[4] = {wv.x, wv.y, wv.z, wv.w};
#pragma unroll
            for (int i = 0; i < 4; i++)
#pragma unroll
                for (int j = 0; j < 4; j++) acc[i][j] = fmaf(ar[i], wr[j], acc[i][j]);
        }
        __syncthreads();
    }
#pragma unroll
    for (int i = 0; i < 4; i++) {
        float4 r = make_float4(acc[i][0], acc[i][1], acc[i][2], acc[i][3]);
        *(float4*)&C[(bm + tm + i) * Hv + bn + tn] = r;
    }
}

// ---------------------------------------------------------------------------
// Score kernel: scores[b,q,k] = sum_h w_v[h] * tanh(qp+kp), tanh in f16x2.
// Grid 512: block = 8 queries x 256 keys (half of K). 8 warps:
//   warp w -> queries {2*(w>>1), +1}, key-subtile (w&1)*32. Keys tiled by 64.
// q/k tiles stored in smem pre-converted to half2, XOR-swizzled 8B chunks.
// smem: qsh [8][64] uint2 (4KB) | wv [256] f32 (1KB) | kbh [64][64] uint2 (32KB)
// ---------------------------------------------------------------------------
__global__ __launch_bounds__(256) void score_kernel(
    const float* __restrict__ qp, const float* __restrict__ kp,
    const float* __restrict__ wv_g, float* __restrict__ scores)
{
    extern __shared__ char smA[];
    uint2* qsh = (uint2*)smA;                       // [8][64] : (q, 4h) chunks
    float* wv  = (float*)(smA + 4096);              // [256]
    uint2* kbh = (uint2*)(smA + 4096 + 1024);       // [64][64] swizzled

    const int tid  = threadIdx.x;
    const int lane = tid & 31;
    const int w    = tid >> 5;
    const int khalf = blockIdx.x & 1;
    const int qt    = blockIdx.x >> 1;
    const int b     = qt >> 6;
    const int qbase = (qt & 63) * 8;

    // q tile -> half2 smem
#pragma unroll
    for (int j = 0; j < 2; j++) {
        int idx = j * 256 + tid;
        int r = idx >> 6, c = idx & 63;
        float4 v = *(const float4*)&qp[(size_t)((b * Qv + qbase + r) * Hv) + c * 4];
        __half2 ha = __floats2half2_rn(v.x, v.y);
        __half2 hb = __floats2half2_rn(v.z, v.w);
        uint2 u; u.x = *(unsigned*)&ha; u.y = *(unsigned*)&hb;
        qsh[r * 64 + c] = u;
    }
    if (tid < 64) *(float4*)&wv[tid * 4] = *(const float4*)&wv_g[tid * 4];

    const int qg   = w >> 1;
    const int ksub = w & 1;
    const int row  = ksub * 32 + lane;
    const int q0   = qg * 2;

    for (int kt = 0; kt < 4; kt++) {
        __syncthreads();   // kbh free (also covers qsh/wv on first iter)
        const int keybase = khalf * 256 + kt * 64;
#pragma unroll
        for (int j = 0; j < 16; j++) {
            int idx = j * 256 + tid;
            int r = idx >> 6, c = idx & 63;
            float4 v = *(const float4*)&kp[(size_t)((b * Kv + keybase + r) * Hv) + c * 4];
            __half2 ha = __floats2half2_rn(v.x, v.y);
            __half2 hb = __floats2half2_rn(v.z, v.w);
            uint2 u; u.x = *(unsigned*)&ha; u.y = *(unsigned*)&hb;
            kbh[r * 64 + (c ^ (r & 31))] = u;
        }
        __syncthreads();

        float a00 = 0.f, a01 = 0.f, a10 = 0.f, a11 = 0.f;
#pragma unroll 8
        for (int h4 = 0; h4 < 64; h4++) {
            uint2 ku = kbh[row * 64 + (h4 ^ lane)];
            __half2 k2a = *(__half2*)&ku.x;
            __half2 k2b = *(__half2*)&ku.y;
            uint2 qu0 = qsh[q0 * 64 + h4];
            uint2 qu1 = qsh[(q0 + 1) * 64 + h4];
            float4 wvv = *(const float4*)&wv[h4 * 4];

            __half2 t0a = tanh2_ap(__hadd2(*(__half2*)&qu0.x, k2a));
            __half2 t0b = tanh2_ap(__hadd2(*(__half2*)&qu0.y, k2b));
            __half2 t1a = tanh2_ap(__hadd2(*(__half2*)&qu1.x, k2a));
            __half2 t1b = tanh2_ap(__hadd2(*(__half2*)&qu1.y, k2b));
            float2 f0a = __half22float2(t0a);
            float2 f0b = __half22float2(t0b);
            float2 f1a = __half22float2(t1a);
            float2 f1b = __half22float2(t1b);
            a00 = fmaf(wvv.x, f0a.x, a00); a01 = fmaf(wvv.y, f0a.y, a01);
            a00 = fmaf(wvv.z, f0b.x, a00); a01 = fmaf(wvv.w, f0b.y, a01);
            a10 = fmaf(wvv.x, f1a.x, a10); a11 = fmaf(wvv.y, f1a.y, a11);
            a10 = fmaf(wvv.z, f1b.x, a10); a11 = fmaf(wvv.w, f1b.y, a11);
        }
        const int key = keybase + row;
        scores[(size_t)((b * Qv + qbase + q0) * Kv) + key]     = a00 + a01;
        scores[(size_t)((b * Qv + qbase + q0 + 1) * Kv) + key] = a10 + a11;
    }
}

// ---------------------------------------------------------------------------
// Softmax + PV. Grid 256: block = 8 queries. 8 warps.
// Softmax: warp w owns query w (reads scores from global, coalesced).
// PV: warp w -> qgroup (w&1)*4..+4, dim-quarter (w>>1)*64; lane owns 2 dims.
// smem: ps [8][512] f32 (16KB) | vb [32][256] f32 (32KB)
// ---------------------------------------------------------------------------
__global__ __launch_bounds__(256) void softmax_pv_kernel(
    const float* __restrict__ scores, const float* __restrict__ V,
    float* __restrict__ out)
{
    extern __shared__ float smB[];
    float* ps = smB;            // [8][512]
    float* vb = smB + 8 * Kv;   // [32][256]

    const int tid  = threadIdx.x;
    const int lane = tid & 31;
    const int w    = tid >> 5;
    const int b     = blockIdx.x >> 6;
    const int qbase = (blockIdx.x & 63) * 8;

    // ---- softmax: warp w handles query qbase+w over 512 scores ----
    {
        const float LOG2E = 1.4426950408889634f;
        const float* src = &scores[(size_t)((b * Qv + qbase + w) * Kv)];
        float4 xv[4];
        float mx = -1e30f;
#pragma unroll
        for (int j = 0; j < 4; j++) {
            xv[j] = *(const float4*)&src[j * 128 + lane * 4];
            mx = fmaxf(mx, fmaxf(fmaxf(xv[j].x, xv[j].y), fmaxf(xv[j].z, xv[j].w)));
        }
#pragma unroll
        for (int off = 16; off > 0; off >>= 1)
            mx = fmaxf(mx, __shfl_xor_sync(0xffffffffu, mx, off));
        float s = 0.f;
#pragma unroll
        for (int j = 0; j < 4; j++) {
            xv[j].x = ex2_ap((xv[j].x - mx) * LOG2E);
            xv[j].y = ex2_ap((xv[j].y - mx) * LOG2E);
            xv[j].z = ex2_ap((xv[j].z - mx) * LOG2E);
            xv[j].w = ex2_ap((xv[j].w - mx) * LOG2E);
            s += xv[j].x + xv[j].y + xv[j].z + xv[j].w;
        }
#pragma unroll
        for (int off = 16; off > 0; off >>= 1)
            s += __shfl_xor_sync(0xffffffffu, s, off);
        float inv = __fdividef(1.f, s);
#pragma unroll
        for (int j = 0; j < 4; j++) {
            xv[j].x *= inv; xv[j].y *= inv; xv[j].z *= inv; xv[j].w *= inv;
            *(float4*)&ps[w * Kv + j * 128 + lane * 4] = xv[j];
        }
    }

    // ---- PV ----
    const int qg = w & 1;          // query group: qbase + 4*qg + j
    const int dq = w >> 1;         // dim quarter
    const int dof = dq * 64 + lane * 2;

    float2 acc[4];
#pragma unroll
    for (int j = 0; j < 4; j++) acc[j] = make_float2(0.f, 0.f);

    for (int kt = 0; kt < Kv; kt += 32) {
        __syncthreads();   // vb free (first iter: also ps ready)
#pragma unroll
        for (int j = 0; j < 8; j++) {
            int idx = j * 256 + tid;
            int r = idx >> 6, c = idx & 63;
            *(float4*)&vb[r * Hv + c * 4] =
                *(const float4*)&V[(size_t)((b * Kv + kt + r) * Hv) + c * 4];
        }
        __syncthreads();

#pragma unroll 2
        for (int kk4 = 0; kk4 < 8; kk4++) {
            float p[4][4];
#pragma unroll
            for (int j = 0; j < 4; j++) {
                float4 p4 = *(const float4*)&ps[(qg * 4 + j) * Kv + kt + kk4 * 4];
                p[j][0] = p4.x; p[j][1] = p4.y; p[j][2] = p4.z; p[j][3] = p4.w;
            }
#pragma unroll
            for (int kk = 0; kk < 4; kk++) {
                float2 v = *(const float2*)&vb[(kk4 * 4 + kk) * Hv + dof];
#pragma unroll
                for (int j = 0; j < 4; j++) {
                    acc[j].x = fmaf(p[j][kk], v.x, acc[j].x);
                    acc[j].y = fmaf(p[j][kk], v.y, acc[j].y);
                }
            }
        }
    }
#pragma unroll
    for (int j = 0; j < 4; j++) {
        *(float2*)&out[(size_t)((b * Qv + qbase + qg * 4 + j) * Hv) + dof] = acc[j];
    }
}

extern "C" void kernel_launch(void* const* d_in, const int* in_sizes, int n_in,
                              void* d_out, int out_size)
{
    const float* queries = (const float*)d_in[0];
    const float* keys    = (const float*)d_in[1];
    const float* values  = (const float*)d_in[2];
    const float* W_q     = (const float*)d_in[3];
    const float* W_k     = (const float*)d_in[4];
    const float* w_v     = (const float*)d_in[5];
    float* out = (float*)d_out;

    float *qp, *kp, *sc;
    cudaGetSymbolAddress((void**)&qp, g_qp);
    cudaGetSymbolAddress((void**)&kp, g_kp);
    cudaGetSymbolAddress((void**)&sc, g_sc);

    proj_kernel<<<dim3(4, 32, 2), 256>>>(queries, W_q, qp, keys, W_k, kp);

    const int smA = 4096 + 1024 + 64 * 64 * 8;    // 37888 B
    cudaFuncSetAttribute(score_kernel, cudaFuncAttributeMaxDynamicSharedMemorySize, smA);
    score_kernel<<<512, 256, smA>>>(qp, kp, w_v, sc);

    const int smB = (8 * Kv + 32 * Hv) * (int)sizeof(float);  // 49152 B
    cudaFuncSetAttribute(softmax_pv_kernel, cudaFuncAttributeMaxDynamicSharedMemorySize, smB);
    softmax_pv_kernel<<<256, 256, smB>>>(sc, values, out);
}

// round 3
// speedup vs baseline: 1.2455x; 1.0807x over previous
#include <cuda_runtime.h>
#include <cuda_fp16.h>

// AdditiveAttention: out = softmax_k( sum_h w_v[h]*tanh(qp[q,h]+kp[k,h]) ) @ V
// B=4, Q=K=512, H=256, fp32 in/out.
// proj (f32 GEMM -> f16 out) -> score (f16x2 tanh, f32 accum) -> softmax+PV (f32).

#define Bv 4
#define Qv 512
#define Kv 512
#define Hv 256
#define MROWS 2048

__device__ uint4 g_qph[MROWS * Hv / 8];   // projected q, f16
__device__ uint4 g_kph[MROWS * Hv / 8];   // projected k, f16
__device__ float g_sc[Bv * Qv * Kv];      // scores, 4MB

__device__ __forceinline__ __half2 tanh2_ap(__half2 x) {
    unsigned xi = *(unsigned*)&x, yi;
    asm("tanh.approx.f16x2 %0, %1;" : "=r"(yi) : "r"(xi));
    return *(__half2*)&yi;
}
__device__ __forceinline__ float ex2_ap(float x) {
    float y;
    asm("ex2.approx.f32 %0, %1;" : "=f"(y) : "f"(x));
    return y;
}
__device__ __forceinline__ void cp_async16(void* smem_dst, const void* gsrc) {
    unsigned s = (unsigned)__cvta_generic_to_shared(smem_dst);
    asm volatile("cp.async.cg.shared.global [%0], [%1], 16;\n" :: "r"(s), "l"(gsrc));
}
__device__ __forceinline__ void cp_commit() {
    asm volatile("cp.async.commit_group;\n");
}
__device__ __forceinline__ __half2 u2h(unsigned u) { return *(__half2*)&u; }

// ---------------------------------------------------------------------------
// Projection GEMM: C[m,o] = sum_h A[m,h]*W[o,h], f32 compute, f16 output.
// 64x64 tile, k-chunk 16, 4x4 microtile, register-prefetch double buffer.
// ---------------------------------------------------------------------------
__global__ __launch_bounds__(256) void proj_kernel(
    const float* __restrict__ A0, const float* __restrict__ W0, __half* __restrict__ C0,
    const float* __restrict__ A1, const float* __restrict__ W1, __half* __restrict__ C1)
{
    const float* A; const float* W; __half* C;
    if (blockIdx.z == 0) { A = A0; W = W0; C = C0; }
    else                 { A = A1; W = W1; C = C1; }

    __shared__ float As[16 * 68];
    __shared__ float Ws[16 * 68];

    const int tid = threadIdx.x;
    const int bm = blockIdx.y * 64;
    const int bn = blockIdx.x * 64;
    const int lr = tid >> 2;
    const int lc = (tid & 3) << 2;
    const int tm = (tid >> 4) << 2;
    const int tn = (tid & 15) << 2;

    const float4* A4 = (const float4*)A;
    const float4* W4 = (const float4*)W;
    const int arow = bm + lr;
    const int wrow = bn + lr;
    const int ccol = tid & 3;

    float acc[4][4];
#pragma unroll
    for (int i = 0; i < 4; i++)
#pragma unroll
        for (int j = 0; j < 4; j++) acc[i][j] = 0.f;

    float4 a = A4[arow * 64 + ccol];
    float4 w = W4[wrow * 64 + ccol];

    for (int k0 = 0; k0 < Hv; k0 += 16) {
        As[(lc + 0) * 68 + lr] = a.x; As[(lc + 1) * 68 + lr] = a.y;
        As[(lc + 2) * 68 + lr] = a.z; As[(lc + 3) * 68 + lr] = a.w;
        Ws[(lc + 0) * 68 + lr] = w.x; Ws[(lc + 1) * 68 + lr] = w.y;
        Ws[(lc + 2) * 68 + lr] = w.z; Ws[(lc + 3) * 68 + lr] = w.w;
        __syncthreads();
        if (k0 + 16 < Hv) {
            a = A4[arow * 64 + ((k0 + 16) >> 2) + ccol];
            w = W4[wrow * 64 + ((k0 + 16) >> 2) + ccol];
        }
#pragma unroll
        for (int k = 0; k < 16; k++) {
            float4 av = *(const float4*)&As[k * 68 + tm];
            float4 wv = *(const float4*)&Ws[k * 68 + tn];
            float ar[4] = {av.x, av.y, av.z, av.w};
            float wr[4] = {wv.x, wv.y, wv.z, wv.w};
#pragma unroll
            for (int i = 0; i < 4; i++)
#pragma unroll
                for (int j = 0; j < 4; j++) acc[i][j] = fmaf(ar[i], wr[j], acc[i][j]);
        }
        __syncthreads();
    }
#pragma unroll
    for (int i = 0; i < 4; i++) {
        __half2 h0 = __floats2half2_rn(acc[i][0], acc[i][1]);
        __half2 h1 = __floats2half2_rn(acc[i][2], acc[i][3]);
        uint2 u; u.x = *(unsigned*)&h0; u.y = *(unsigned*)&h1;
        *(uint2*)&C[(bm + tm + i) * Hv + bn + tn] = u;
    }
}

// ---------------------------------------------------------------------------
// Score kernel: scores[b,q,k] = sum_h w_v[h]*tanh(qp+kp), f16x2 tanh, f32 acc.
// Grid 512: block = 8 queries x 256 keys. Warp -> 2 queries x 32-key row.
// k tiles (64 keys, 32KB) double-buffered via cp.async, 16B XOR swizzle.
// smem: qsh uint4[256] 4KB | wv f32[256] 1KB | kbh uint4[2][2048] 64KB = 69.5KB
// ---------------------------------------------------------------------------
__global__ __launch_bounds__(256) void score_kernel(
    const uint4* __restrict__ qp, const uint4* __restrict__ kp,
    const float* __restrict__ wv_g, float* __restrict__ scores)
{
    extern __shared__ char smA[];
    uint4* qsh = (uint4*)smA;                       // [8][32]
    float* wv  = (float*)(smA + 4096);              // [256]
    uint4* kbh = (uint4*)(smA + 4096 + 1024);       // [2][64][32] swizzled

    const int tid  = threadIdx.x;
    const int lane = tid & 31;
    const int w    = tid >> 5;
    const int khalf = blockIdx.x & 1;
    const int qt    = blockIdx.x >> 1;
    const int b     = qt >> 6;
    const int qbase = (qt & 63) * 8;

    // q tile: 8 rows x 32 uint4 (row = 256 halves = 32 uint4)
    {
        int r = tid >> 5, c = tid & 31;
        qsh[tid] = qp[(size_t)(b * Qv + qbase + r) * 32 + c];
    }
    if (tid < 64) *(float4*)&wv[tid * 4] = *(const float4*)&wv_g[tid * 4];

    const int keyhb = khalf * 256;
    const uint4* ksrc_base = kp + (size_t)(b * Kv + keyhb) * 32;

    // prefetch tile 0
    {
        uint4* dst = kbh;
#pragma unroll
        for (int j = 0; j < 8; j++) {
            int idx = j * 256 + tid;
            int r = idx >> 5, c = idx & 31;
            cp_async16(&dst[r * 32 + (c ^ (r & 31))], &ksrc_base[r * 32 + c]);
        }
        cp_commit();
    }

    const int qg  = w >> 1;
    const int row = (w & 1) * 32 + lane;
    const int q0  = qg * 2;

    for (int kt = 0; kt < 4; kt++) {
        if (kt < 3) {
            uint4* dst = kbh + ((kt + 1) & 1) * 2048;
            const uint4* src = ksrc_base + (size_t)(kt + 1) * 64 * 32;
#pragma unroll
            for (int j = 0; j < 8; j++) {
                int idx = j * 256 + tid;
                int r = idx >> 5, c = idx & 31;
                cp_async16(&dst[r * 32 + (c ^ (r & 31))], &src[r * 32 + c]);
            }
            cp_commit();
            asm volatile("cp.async.wait_group 1;\n");
        } else {
            asm volatile("cp.async.wait_group 0;\n");
        }
        __syncthreads();

        const uint4* kb = kbh + (kt & 1) * 2048;
        float a00 = 0.f, a01 = 0.f, a10 = 0.f, a11 = 0.f;
#pragma unroll 8
        for (int h8 = 0; h8 < 32; h8++) {
            uint4 ku  = kb[row * 32 + (h8 ^ lane)];
            uint4 qu0 = qsh[q0 * 32 + h8];
            uint4 qu1 = qsh[q0 * 32 + 32 + h8];
            float4 wa = *(const float4*)&wv[h8 * 8];
            float4 wb = *(const float4*)&wv[h8 * 8 + 4];
            __half2 k0 = u2h(ku.x), k1 = u2h(ku.y), k2 = u2h(ku.z), k3 = u2h(ku.w);
            float2 f;
            f = __half22float2(tanh2_ap(__hadd2(u2h(qu0.x), k0)));
            a00 = fmaf(wa.x, f.x, a00); a01 = fmaf(wa.y, f.y, a01);
            f = __half22float2(tanh2_ap(__hadd2(u2h(qu0.y), k1)));
            a00 = fmaf(wa.z, f.x, a00); a01 = fmaf(wa.w, f.y, a01);
            f = __half22float2(tanh2_ap(__hadd2(u2h(qu0.z), k2)));
            a00 = fmaf(wb.x, f.x, a00); a01 = fmaf(wb.y, f.y, a01);
            f = __half22float2(tanh2_ap(__hadd2(u2h(qu0.w), k3)));
            a00 = fmaf(wb.z, f.x, a00); a01 = fmaf(wb.w, f.y, a01);
            f = __half22float2(tanh2_ap(__hadd2(u2h(qu1.x), k0)));
            a10 = fmaf(wa.x, f.x, a10); a11 = fmaf(wa.y, f.y, a11);
            f = __half22float2(tanh2_ap(__hadd2(u2h(qu1.y), k1)));
            a10 = fmaf(wa.z, f.x, a10); a11 = fmaf(wa.w, f.y, a11);
            f = __half22float2(tanh2_ap(__hadd2(u2h(qu1.z), k2)));
            a10 = fmaf(wb.x, f.x, a10); a11 = fmaf(wb.y, f.y, a11);
            f = __half22float2(tanh2_ap(__hadd2(u2h(qu1.w), k3)));
            a10 = fmaf(wb.z, f.x, a10); a11 = fmaf(wb.w, f.y, a11);
        }
        const int key = keyhb + kt * 64 + row;
        scores[(size_t)(b * Qv + qbase + q0) * Kv + key]       = a00 + a01;
        scores[(size_t)(b * Qv + qbase + q0 + 1) * Kv + key]   = a10 + a11;
        __syncthreads();
    }
}

// ---------------------------------------------------------------------------
// Softmax + PV. Grid 256: block = 8 queries. Warp w: softmax for query w,
// then PV for qgroup (w&1)*4..+4, dim quarter (w>>1)*64 (lane: 2 dims).
// V tiles (32 keys, 32KB) double-buffered via cp.async.
// smem: ps f32[8][512] 16KB | vb f32[2][32][256] 64KB = 80KB
// ---------------------------------------------------------------------------
__global__ __launch_bounds__(256) void softmax_pv_kernel(
    const float* __restrict__ scores, const float* __restrict__ V,
    float* __restrict__ out)
{
    extern __shared__ float smB[];
    float* ps = smB;              // [8][512]
    float* vb = smB + 8 * Kv;     // [2][32][256]

    const int tid  = threadIdx.x;
    const int lane = tid & 31;
    const int w    = tid >> 5;
    const int b     = blockIdx.x >> 6;
    const int qbase = (blockIdx.x & 63) * 8;

    const float4* V4 = (const float4*)V;
    const float4* vsrc_base = V4 + (size_t)(b * Kv) * 64;

    // prefetch V tile 0
    {
        float* dst = vb;
#pragma unroll
        for (int j = 0; j < 8; j++) {
            int idx = j * 256 + tid;
            int r = idx >> 6, c = idx & 63;
            cp_async16(&dst[r * Hv + c * 4], &vsrc_base[r * 64 + c]);
        }
        cp_commit();
    }

    // ---- softmax: warp w handles query qbase+w ----
    {
        const float LOG2E = 1.4426950408889634f;
        const float* src = &scores[(size_t)(b * Qv + qbase + w) * Kv];
        float4 xv[4];
        float mx = -1e30f;
#pragma unroll
        for (int j = 0; j < 4; j++) {
            xv[j] = *(const float4*)&src[j * 128 + lane * 4];
            mx = fmaxf(mx, fmaxf(fmaxf(xv[j].x, xv[j].y), fmaxf(xv[j].z, xv[j].w)));
        }
#pragma unroll
        for (int off = 16; off > 0; off >>= 1)
            mx = fmaxf(mx, __shfl_xor_sync(0xffffffffu, mx, off));
        float s = 0.f;
#pragma unroll
        for (int j = 0; j < 4; j++) {
            xv[j].x = ex2_ap((xv[j].x - mx) * LOG2E);
            xv[j].y = ex2_ap((xv[j].y - mx) * LOG2E);
            xv[j].z = ex2_ap((xv[j].z - mx) * LOG2E);
            xv[j].w = ex2_ap((xv[j].w - mx) * LOG2E);
            s += xv[j].x + xv[j].y + xv[j].z + xv[j].w;
        }
#pragma unroll
        for (int off = 16; off > 0; off >>= 1)
            s += __shfl_xor_sync(0xffffffffu, s, off);
        float inv = __fdividef(1.f, s);
#pragma unroll
        for (int j = 0; j < 4; j++) {
            xv[j].x *= inv; xv[j].y *= inv; xv[j].z *= inv; xv[j].w *= inv;
            *(float4*)&ps[w * Kv + j * 128 + lane * 4] = xv[j];
        }
    }

    // ---- PV ----
    const int qg  = w & 1;
    const int dof = (w >> 1) * 64 + lane * 2;

    float2 acc[4];
#pragma unroll
    for (int j = 0; j < 4; j++) acc[j] = make_float2(0.f, 0.f);

    for (int kt = 0; kt < 16; kt++) {
        if (kt < 15) {
            float* dst = vb + ((kt + 1) & 1) * 32 * Hv;
            const float4* src = vsrc_base + (size_t)(kt + 1) * 32 * 64;
#pragma unroll
            for (int j = 0; j < 8; j++) {
                int idx = j * 256 + tid;
                int r = idx >> 6, c = idx & 63;
                cp_async16(&dst[r * Hv + c * 4], &src[r * 64 + c]);
            }
            cp_commit();
            asm volatile("cp.async.wait_group 1;\n");
        } else {
            asm volatile("cp.async.wait_group 0;\n");
        }
        __syncthreads();

        const float* vt = vb + (kt & 1) * 32 * Hv;
#pragma unroll 2
        for (int kk4 = 0; kk4 < 8; kk4++) {
            float p[4][4];
#pragma unroll
            for (int j = 0; j < 4; j++) {
                float4 p4 = *(const float4*)&ps[(qg * 4 + j) * Kv + kt * 32 + kk4 * 4];
                p[j][0] = p4.x; p[j][1] = p4.y; p[j][2] = p4.z; p[j][3] = p4.w;
            }
#pragma unroll
            for (int kk = 0; kk < 4; kk++) {
                float2 v = *(const float2*)&vt[(kk4 * 4 + kk) * Hv + dof];
#pragma unroll
                for (int j = 0; j < 4; j++) {
                    acc[j].x = fmaf(p[j][kk], v.x, acc[j].x);
                    acc[j].y = fmaf(p[j][kk], v.y, acc[j].y);
                }
            }
        }
        __syncthreads();
    }
#pragma unroll
    for (int j = 0; j < 4; j++) {
        *(float2*)&out[(size_t)(b * Qv + qbase + qg * 4 + j) * Hv + dof] = acc[j];
    }
}

extern "C" void kernel_launch(void* const* d_in, const int* in_sizes, int n_in,
                              void* d_out, int out_size)
{
    const float* queries = (const float*)d_in[0];
    const float* keys    = (const float*)d_in[1];
    const float* values  = (const float*)d_in[2];
    const float* W_q     = (const float*)d_in[3];
    const float* W_k     = (const float*)d_in[4];
    const float* w_v     = (const float*)d_in[5];
    float* out = (float*)d_out;

    uint4 *qph, *kph; float* sc;
    cudaGetSymbolAddress((void**)&qph, g_qph);
    cudaGetSymbolAddress((void**)&kph, g_kph);
    cudaGetSymbolAddress((void**)&sc, g_sc);

    proj_kernel<<<dim3(4, 32, 2), 256>>>(queries, W_q, (__half*)qph,
                                         keys, W_k, (__half*)kph);

    const int smA = 4096 + 1024 + 2 * 2048 * 16;   // 70656 B
    cudaFuncSetAttribute(score_kernel, cudaFuncAttributeMaxDynamicSharedMemorySize, smA);
    score_kernel<<<512, 256, smA>>>(qph, kph, w_v, sc);

    const int smB = (8 * Kv + 2 * 32 * Hv) * (int)sizeof(float);  // 81920 B
    cudaFuncSetAttribute(softmax_pv_kernel, cudaFuncAttributeMaxDynamicSharedMemorySize, smB);
    softmax_pv_kernel<<<256, 256, smB>>>(sc, values, out);
}

// round 4
// speedup vs baseline: 1.2757x; 1.0242x over previous
#include <cuda_runtime.h>
#include <cuda_fp16.h>

// AdditiveAttention: out = softmax_k( sum_h w_v[h]*tanh(qp[q,h]+kp[k,h]) ) @ V
// B=4, Q=K=512, H=256, fp32 in/out.
// proj (f32 GEMM -> f16) -> score (persistent, f16x2 tanh, f32 acc) -> softmax+PV.

#define Bv 4
#define Qv 512
#define Kv 512
#define Hv 256
#define MROWS 2048
#define SGRID 456               // 3 blocks/SM x 152 SMs, one exact wave
#define NUNITS 2048             // (2048/8 q-tiles) x (512/64 k-tiles)

__device__ uint4 g_qph[MROWS * Hv / 8];   // projected q, f16
__device__ uint4 g_kph[MROWS * Hv / 8];   // projected k, f16
__device__ float g_sc[Bv * Qv * Kv];      // scores, 4MB

__device__ __forceinline__ __half2 tanh2_ap(__half2 x) {
    unsigned xi = *(unsigned*)&x, yi;
    asm("tanh.approx.f16x2 %0, %1;" : "=r"(yi) : "r"(xi));
    return *(__half2*)&yi;
}
__device__ __forceinline__ float ex2_ap(float x) {
    float y;
    asm("ex2.approx.f32 %0, %1;" : "=f"(y) : "f"(x));
    return y;
}
__device__ __forceinline__ void cp_async16(void* smem_dst, const void* gsrc) {
    unsigned s = (unsigned)__cvta_generic_to_shared(smem_dst);
    asm volatile("cp.async.cg.shared.global [%0], [%1], 16;\n" :: "r"(s), "l"(gsrc));
}
__device__ __forceinline__ void cp_commit() {
    asm volatile("cp.async.commit_group;\n");
}
__device__ __forceinline__ __half2 u2h(unsigned u) { return *(__half2*)&u; }

// ---------------------------------------------------------------------------
// Projection GEMM: C[m,o] = sum_h A[m,h]*W[o,h], f32 compute, f16 output.
// 32x64 tile (grid 512 -> ~3.4 blocks/SM), k-chunk 16, 2x4 microtile,
// register-prefetch double buffer.
// ---------------------------------------------------------------------------
__global__ __launch_bounds__(256) void proj_kernel(
    const float* __restrict__ A0, const float* __restrict__ W0, __half* __restrict__ C0,
    const float* __restrict__ A1, const float* __restrict__ W1, __half* __restrict__ C1)
{
    const float* A; const float* W; __half* C;
    if (blockIdx.z == 0) { A = A0; W = W0; C = C0; }
    else                 { A = A1; W = W1; C = C1; }

    __shared__ float As[16 * 36];   // [k][m] m=32 pad->36
    __shared__ float Ws[16 * 68];   // [k][n] n=64 pad->68

    const int tid = threadIdx.x;
    const int bm = blockIdx.y * 32;
    const int bn = blockIdx.x * 64;

    const int wr = tid >> 2;            // W row 0..63
    const int lc = (tid & 3) << 2;      // k-col 0,4,8,12
    const int ar = tid >> 2;            // A row (only tid<128 -> 0..31)
    const bool doA = (tid < 128);

    const int tm = (tid >> 4) << 1;     // 0..30
    const int tn = (tid & 15) << 2;     // 0..60

    const float4* A4 = (const float4*)A;
    const float4* W4 = (const float4*)W;
    const int ccol = tid & 3;

    float acc[2][4];
#pragma unroll
    for (int i = 0; i < 2; i++)
#pragma unroll
        for (int j = 0; j < 4; j++) acc[i][j] = 0.f;

    float4 a = doA ? A4[(bm + ar) * 64 + ccol] : make_float4(0, 0, 0, 0);
    float4 w = W4[(bn + wr) * 64 + ccol];

    for (int k0 = 0; k0 < Hv; k0 += 16) {
        if (doA) {
            As[(lc + 0) * 36 + ar] = a.x; As[(lc + 1) * 36 + ar] = a.y;
            As[(lc + 2) * 36 + ar] = a.z; As[(lc + 3) * 36 + ar] = a.w;
        }
        Ws[(lc + 0) * 68 + wr] = w.x; Ws[(lc + 1) * 68 + wr] = w.y;
        Ws[(lc + 2) * 68 + wr] = w.z; Ws[(lc + 3) * 68 + wr] = w.w;
        __syncthreads();
        if (k0 + 16 < Hv) {
            int c4 = ((k0 + 16) >> 2) + ccol;
            if (doA) a = A4[(bm + ar) * 64 + c4];
            w = W4[(bn + wr) * 64 + c4];
        }
#pragma unroll
        for (int k = 0; k < 16; k++) {
            float2 av = *(const float2*)&As[k * 36 + tm];
            float4 wv = *(const float4*)&Ws[k * 68 + tn];
            float ar2[2] = {av.x, av.y};
            float wr4[4] = {wv.x, wv.y, wv.z, wv.w};
#pragma unroll
            for (int i = 0; i < 2; i++)
#pragma unroll
                for (int j = 0; j < 4; j++) acc[i][j] = fmaf(ar2[i], wr4[j], acc[i][j]);
        }
        __syncthreads();
    }
#pragma unroll
    for (int i = 0; i < 2; i++) {
        __half2 h0 = __floats2half2_rn(acc[i][0], acc[i][1]);
        __half2 h1 = __floats2half2_rn(acc[i][2], acc[i][3]);
        uint2 u; u.x = *(unsigned*)&h0; u.y = *(unsigned*)&h1;
        *(uint2*)&C[(bm + tm + i) * Hv + bn + tn] = u;
    }
}

// ---------------------------------------------------------------------------
// Score kernel (persistent): unit = 8 queries x 64 keys; 2048 units over
// grid 456, block b takes units b, b+456, ... Cross-unit cp.async double
// buffering of (k 32KB + q 4KB) stages.
// smem: wv f32[256] 1KB | qsh uint4[2][256] 8KB | kbh uint4[2][2048] 64KB
// Warp w: queries q0=2*(w>>1),q0+1; keys row (w&1)*32+lane of the 64-key tile.
// ---------------------------------------------------------------------------
struct ScoreSmem {
    float wv[256];
    uint4 qsh[2][256];
    uint4 kbh[2][2048];
};

__device__ __forceinline__ void score_prefetch(
    ScoreSmem* sm, const uint4* qp, const uint4* kp, int u, int p, int tid)
{
    const int qt = u >> 3;
    const int kt = u & 7;
    const int b = qt >> 6;
    const int qbase = (qt & 63) * 8;
    const uint4* qsrc = qp + (size_t)(b * Qv + qbase) * 32;
    cp_async16(&sm->qsh[p][tid], &qsrc[tid]);
    const uint4* ksrc = kp + (size_t)(b * Kv + kt * 64) * 32;
#pragma unroll
    for (int j = 0; j < 8; j++) {
        int idx = j * 256 + tid;
        int r = idx >> 5, c = idx & 31;
        cp_async16(&sm->kbh[p][r * 32 + (c ^ (r & 31))], &ksrc[r * 32 + c]);
    }
}

__global__ __launch_bounds__(256) void score_kernel(
    const uint4* __restrict__ qp, const uint4* __restrict__ kp,
    const float* __restrict__ wv_g, float* __restrict__ scores)
{
    extern __shared__ char smraw[];
    ScoreSmem* sm = (ScoreSmem*)smraw;

    const int tid  = threadIdx.x;
    const int lane = tid & 31;
    const int w    = tid >> 5;

    if (tid < 64) *(float4*)&sm->wv[tid * 4] = *(const float4*)&wv_g[tid * 4];

    const int qg  = w >> 1;
    const int rowk = (w & 1) * 32 + lane;
    const int q0  = qg * 2;

    int u = blockIdx.x;
    score_prefetch(sm, qp, kp, u, 0, tid);
    cp_commit();
    int p = 0;

    while (u < NUNITS) {
        int un = u + SGRID;
        if (un < NUNITS) {
            score_prefetch(sm, qp, kp, un, p ^ 1, tid);
            cp_commit();
            asm volatile("cp.async.wait_group 1;\n");
        } else {
            asm volatile("cp.async.wait_group 0;\n");
        }
        __syncthreads();

        const uint4* kb = sm->kbh[p];
        const uint4* qs = sm->qsh[p];
        float a00 = 0.f, a01 = 0.f, a10 = 0.f, a11 = 0.f;
#pragma unroll 8
        for (int h8 = 0; h8 < 32; h8++) {
            uint4 ku  = kb[rowk * 32 + (h8 ^ lane)];
            uint4 qu0 = qs[q0 * 32 + h8];
            uint4 qu1 = qs[q0 * 32 + 32 + h8];
            float4 wa = *(const float4*)&sm->wv[h8 * 8];
            float4 wb = *(const float4*)&sm->wv[h8 * 8 + 4];
            __half2 k0 = u2h(ku.x), k1 = u2h(ku.y), k2 = u2h(ku.z), k3 = u2h(ku.w);
            float2 f;
            f = __half22float2(tanh2_ap(__hadd2(u2h(qu0.x), k0)));
            a00 = fmaf(wa.x, f.x, a00); a01 = fmaf(wa.y, f.y, a01);
            f = __half22float2(tanh2_ap(__hadd2(u2h(qu0.y), k1)));
            a00 = fmaf(wa.z, f.x, a00); a01 = fmaf(wa.w, f.y, a01);
            f = __half22float2(tanh2_ap(__hadd2(u2h(qu0.z), k2)));
            a00 = fmaf(wb.x, f.x, a00); a01 = fmaf(wb.y, f.y, a01);
            f = __half22float2(tanh2_ap(__hadd2(u2h(qu0.w), k3)));
            a00 = fmaf(wb.z, f.x, a00); a01 = fmaf(wb.w, f.y, a01);
            f = __half22float2(tanh2_ap(__hadd2(u2h(qu1.x), k0)));
            a10 = fmaf(wa.x, f.x, a10); a11 = fmaf(wa.y, f.y, a11);
            f = __half22float2(tanh2_ap(__hadd2(u2h(qu1.y), k1)));
            a10 = fmaf(wa.z, f.x, a10); a11 = fmaf(wa.w, f.y, a11);
            f = __half22float2(tanh2_ap(__hadd2(u2h(qu1.z), k2)));
            a10 = fmaf(wb.x, f.x, a10); a11 = fmaf(wb.y, f.y, a11);
            f = __half22float2(tanh2_ap(__hadd2(u2h(qu1.w), k3)));
            a10 = fmaf(wb.z, f.x, a10); a11 = fmaf(wb.w, f.y, a11);
        }
        {
            const int qt = u >> 3;
            const int kt = u & 7;
            const int b = qt >> 6;
            const int qbase = (qt & 63) * 8;
            const int key = kt * 64 + rowk;
            scores[(size_t)(b * Qv + qbase + q0) * Kv + key]     = a00 + a01;
            scores[(size_t)(b * Qv + qbase + q0 + 1) * Kv + key] = a10 + a11;
        }
        __syncthreads();
        u = un; p ^= 1;
    }
}

// ---------------------------------------------------------------------------
// Softmax + PV. Grid 256: block = 8 queries. Warp w: softmax for query w,
// then PV for qgroup (w&1)*4..+4, dim quarter (w>>1)*64 (lane: 2 dims).
// V tiles (32 keys, 32KB) double-buffered via cp.async.
// smem: ps f32[8][512] 16KB | vb f32[2][32][256] 64KB = 80KB
// ---------------------------------------------------------------------------
__global__ __launch_bounds__(256) void softmax_pv_kernel(
    const float* __restrict__ scores, const float* __restrict__ V,
    float* __restrict__ out)
{
    extern __shared__ float smB[];
    float* ps = smB;              // [8][512]
    float* vb = smB + 8 * Kv;     // [2][32][256]

    const int tid  = threadIdx.x;
    const int lane = tid & 31;
    const int w    = tid >> 5;
    const int b     = blockIdx.x >> 6;
    const int qbase = (blockIdx.x & 63) * 8;

    const float4* vsrc_base = (const float4*)V + (size_t)(b * Kv) * 64;

    // prefetch V tile 0
#pragma unroll
    for (int j = 0; j < 8; j++) {
        int idx = j * 256 + tid;
        int r = idx >> 6, c = idx & 63;
        cp_async16(&vb[r * Hv + c * 4], &vsrc_base[r * 64 + c]);
    }
    cp_commit();

    // ---- softmax: warp w handles query qbase+w ----
    {
        const float LOG2E = 1.4426950408889634f;
        const float* src = &scores[(size_t)(b * Qv + qbase + w) * Kv];
        float4 xv[4];
        float mx = -1e30f;
#pragma unroll
        for (int j = 0; j < 4; j++) {
            xv[j] = *(const float4*)&src[j * 128 + lane * 4];
            mx = fmaxf(mx, fmaxf(fmaxf(xv[j].x, xv[j].y), fmaxf(xv[j].z, xv[j].w)));
        }
#pragma unroll
        for (int off = 16; off > 0; off >>= 1)
            mx = fmaxf(mx, __shfl_xor_sync(0xffffffffu, mx, off));
        float s = 0.f;
#pragma unroll
        for (int j = 0; j < 4; j++) {
            xv[j].x = ex2_ap((xv[j].x - mx) * LOG2E);
            xv[j].y = ex2_ap((xv[j].y - mx) * LOG2E);
            xv[j].z = ex2_ap((xv[j].z - mx) * LOG2E);
            xv[j].w = ex2_ap((xv[j].w - mx) * LOG2E);
            s += xv[j].x + xv[j].y + xv[j].z + xv[j].w;
        }
#pragma unroll
        for (int off = 16; off > 0; off >>= 1)
            s += __shfl_xor_sync(0xffffffffu, s, off);
        float inv = __fdividef(1.f, s);
#pragma unroll
        for (int j = 0; j < 4; j++) {
            xv[j].x *= inv; xv[j].y *= inv; xv[j].z *= inv; xv[j].w *= inv;
            *(float4*)&ps[w * Kv + j * 128 + lane * 4] = xv[j];
        }
    }

    // ---- PV ----
    const int qg  = w & 1;
    const int dof = (w >> 1) * 64 + lane * 2;

    float2 acc[4];
#pragma unroll
    for (int j = 0; j < 4; j++) acc[j] = make_float2(0.f, 0.f);

    for (int kt = 0; kt < 16; kt++) {
        if (kt < 15) {
            float* dst = vb + ((kt + 1) & 1) * 32 * Hv;
            const float4* src = vsrc_base + (size_t)(kt + 1) * 32 * 64;
#pragma unroll
            for (int j = 0; j < 8; j++) {
                int idx = j * 256 + tid;
                int r = idx >> 6, c = idx & 63;
                cp_async16(&dst[r * Hv + c * 4], &src[r * 64 + c]);
            }
            cp_commit();
            asm volatile("cp.async.wait_group 1;\n");
        } else {
            asm volatile("cp.async.wait_group 0;\n");
        }
        __syncthreads();

        const float* vt = vb + (kt & 1) * 32 * Hv;
#pragma unroll 2
        for (int kk4 = 0; kk4 < 8; kk4++) {
            float p[4][4];
#pragma unroll
            for (int j = 0; j < 4; j++) {
                float4 p4 = *(const float4*)&ps[(qg * 4 + j) * Kv + kt * 32 + kk4 * 4];
                p[j][0] = p4.x; p[j][1] = p4.y; p[j][2] = p4.z; p[j][3] = p4.w;
            }
#pragma unroll
            for (int kk = 0; kk < 4; kk++) {
                float2 v = *(const float2*)&vt[(kk4 * 4 + kk) * Hv + dof];
#pragma unroll
                for (int j = 0; j < 4; j++) {
                    acc[j].x = fmaf(p[j][kk], v.x, acc[j].x);
                    acc[j].y = fmaf(p[j][kk], v.y, acc[j].y);
                }
            }
        }
        __syncthreads();
    }
#pragma unroll
    for (int j = 0; j < 4; j++) {
        *(float2*)&out[(size_t)(b * Qv + qbase + qg * 4 + j) * Hv + dof] = acc[j];
    }
}

extern "C" void kernel_launch(void* const* d_in, const int* in_sizes, int n_in,
                              void* d_out, int out_size)
{
    const float* queries = (const float*)d_in[0];
    const float* keys    = (const float*)d_in[1];
    const float* values  = (const float*)d_in[2];
    const float* W_q     = (const float*)d_in[3];
    const float* W_k     = (const float*)d_in[4];
    const float* w_v     = (const float*)d_in[5];
    float* out = (float*)d_out;

    uint4 *qph, *kph; float* sc;
    cudaGetSymbolAddress((void**)&qph, g_qph);
    cudaGetSymbolAddress((void**)&kph, g_kph);
    cudaGetSymbolAddress((void**)&sc, g_sc);

    proj_kernel<<<dim3(4, 64, 2), 256>>>(queries, W_q, (__half*)qph,
                                         keys, W_k, (__half*)kph);

    const int smA = (int)sizeof(ScoreSmem);   // 1024 + 8192 + 65536 = 74752 B
    cudaFuncSetAttribute(score_kernel, cudaFuncAttributeMaxDynamicSharedMemorySize, smA);
    score_kernel<<<SGRID, 256, smA>>>(qph, kph, w_v, sc);

    const int smB = (8 * Kv + 2 * 32 * Hv) * (int)sizeof(float);  // 81920 B
    cudaFuncSetAttribute(softmax_pv_kernel, cudaFuncAttributeMaxDynamicSharedMemorySize, smB);
    softmax_pv_kernel<<<256, 256, smB>>>(sc, values, out);
}

// round 5
// speedup vs baseline: 1.4190x; 1.1123x over previous
#include <cuda_runtime.h>
#include <cuda_fp16.h>

// AdditiveAttention: out = softmax_k( sum_h w_v[h]*tanh(qp[q,h]+kp[k,h]) ) @ V
// B=4, Q=K=512, H=256, fp32 in/out.
// proj (f32 GEMM -> f16) -> score (persistent, f16 tanh + f16 weighted reduce,
// f32 chunk accum) -> softmax+PV (f32).

#define Bv 4
#define Qv 512
#define Kv 512
#define Hv 256
#define MROWS 2048
#define SGRID 456               // 3 blocks/SM x 152 SMs
#define NUNITS 2048             // (2048/8 q-tiles) x (512/64 k-tiles)

__device__ uint4 g_qph[MROWS * Hv / 8];   // projected q, f16
__device__ uint4 g_kph[MROWS * Hv / 8];   // projected k, f16
__device__ float g_sc[Bv * Qv * Kv];      // scores, 4MB

__device__ __forceinline__ __half2 tanh2_ap(__half2 x) {
    unsigned xi = *(unsigned*)&x, yi;
    asm("tanh.approx.f16x2 %0, %1;" : "=r"(yi) : "r"(xi));
    return *(__half2*)&yi;
}
__device__ __forceinline__ float ex2_ap(float x) {
    float y;
    asm("ex2.approx.f32 %0, %1;" : "=f"(y) : "f"(x));
    return y;
}
__device__ __forceinline__ void cp_async16(void* smem_dst, const void* gsrc) {
    unsigned s = (unsigned)__cvta_generic_to_shared(smem_dst);
    asm volatile("cp.async.cg.shared.global [%0], [%1], 16;\n" :: "r"(s), "l"(gsrc));
}
__device__ __forceinline__ void cp_commit() {
    asm volatile("cp.async.commit_group;\n");
}
__device__ __forceinline__ __half2 u2h(unsigned u) { return *(__half2*)&u; }

// ---------------------------------------------------------------------------
// Projection GEMM (R3 version, measured 22.4us): C[m,o] = sum_h A[m,h]*W[o,h],
// f32 compute, f16 output. 64x64 tile, k-chunk 16, 4x4 microtile,
// register-prefetch double buffer.
// ---------------------------------------------------------------------------
__global__ __launch_bounds__(256) void proj_kernel(
    const float* __restrict__ A0, const float* __restrict__ W0, __half* __restrict__ C0,
    const float* __restrict__ A1, const float* __restrict__ W1, __half* __restrict__ C1)
{
    const float* A; const float* W; __half* C;
    if (blockIdx.z == 0) { A = A0; W = W0; C = C0; }
    else                 { A = A1; W = W1; C = C1; }

    __shared__ float As[16 * 68];
    __shared__ float Ws[16 * 68];

    const int tid = threadIdx.x;
    const int bm = blockIdx.y * 64;
    const int bn = blockIdx.x * 64;
    const int lr = tid >> 2;
    const int lc = (tid & 3) << 2;
    const int tm = (tid >> 4) << 2;
    const int tn = (tid & 15) << 2;

    const float4* A4 = (const float4*)A;
    const float4* W4 = (const float4*)W;
    const int arow = bm + lr;
    const int wrow = bn + lr;
    const int ccol = tid & 3;

    float acc[4][4];
#pragma unroll
    for (int i = 0; i < 4; i++)
#pragma unroll
        for (int j = 0; j < 4; j++) acc[i][j] = 0.f;

    float4 a = A4[arow * 64 + ccol];
    float4 w = W4[wrow * 64 + ccol];

    for (int k0 = 0; k0 < Hv; k0 += 16) {
        As[(lc + 0) * 68 + lr] = a.x; As[(lc + 1) * 68 + lr] = a.y;
        As[(lc + 2) * 68 + lr] = a.z; As[(lc + 3) * 68 + lr] = a.w;
        Ws[(lc + 0) * 68 + lr] = w.x; Ws[(lc + 1) * 68 + lr] = w.y;
        Ws[(lc + 2) * 68 + lr] = w.z; Ws[(lc + 3) * 68 + lr] = w.w;
        __syncthreads();
        if (k0 + 16 < Hv) {
            a = A4[arow * 64 + ((k0 + 16) >> 2) + ccol];
            w = W4[wrow * 64 + ((k0 + 16) >> 2) + ccol];
        }
#pragma unroll
        for (int k = 0; k < 16; k++) {
            float4 av = *(const float4*)&As[k * 68 + tm];
            float4 wv = *(const float4*)&Ws[k * 68 + tn];
            float ar4[4] = {av.x, av.y, av.z, av.w};
            float wr4[4] = {wv.x, wv.y, wv.z, wv.w};
#pragma unroll
            for (int i = 0; i < 4; i++)
#pragma unroll
                for (int j = 0; j < 4; j++) acc[i][j] = fmaf(ar4[i], wr4[j], acc[i][j]);
        }
        __syncthreads();
    }
#pragma unroll
    for (int i = 0; i < 4; i++) {
        __half2 h0 = __floats2half2_rn(acc[i][0], acc[i][1]);
        __half2 h1 = __floats2half2_rn(acc[i][2], acc[i][3]);
        uint2 u; u.x = *(unsigned*)&h0; u.y = *(unsigned*)&h1;
        *(uint2*)&C[(bm + tm + i) * Hv + bn + tn] = u;
    }
}

// ---------------------------------------------------------------------------
// Score kernel (persistent): unit = 8 queries x 64 keys; 2048 units over
// grid 456. Cross-unit cp.async double buffering. w_v held as half2.
// Inner: tanh f16x2; weighted reduction kept in f16 (HMUL2/HFMA2 chain over
// 16 h), flushed to f32 once per chunk -> 4 F2F per h16 instead of 32.
// smem: wvh uint4[32] 512B | qsh uint4[2][256] 8KB | kbh uint4[2][2048] 64KB
// ---------------------------------------------------------------------------
struct ScoreSmem {
    uint4 wvh[32];              // w_v as 256 halves
    uint4 qsh[2][256];
    uint4 kbh[2][2048];
};

__device__ __forceinline__ void score_prefetch(
    ScoreSmem* sm, const uint4* qp, const uint4* kp, int u, int p, int tid)
{
    const int qt = u >> 3;
    const int kt = u & 7;
    const int b = qt >> 6;
    const int qbase = (qt & 63) * 8;
    const uint4* qsrc = qp + (size_t)(b * Qv + qbase) * 32;
    cp_async16(&sm->qsh[p][tid], &qsrc[tid]);
    const uint4* ksrc = kp + (size_t)(b * Kv + kt * 64) * 32;
#pragma unroll
    for (int j = 0; j < 8; j++) {
        int idx = j * 256 + tid;
        int r = idx >> 5, c = idx & 31;
        cp_async16(&sm->kbh[p][r * 32 + (c ^ (r & 31))], &ksrc[r * 32 + c]);
    }
}

__global__ __launch_bounds__(256) void score_kernel(
    const uint4* __restrict__ qp, const uint4* __restrict__ kp,
    const float* __restrict__ wv_g, float* __restrict__ scores)
{
    extern __shared__ char smraw[];
    ScoreSmem* sm = (ScoreSmem*)smraw;

    const int tid  = threadIdx.x;
    const int lane = tid & 31;
    const int w    = tid >> 5;

    if (tid < 32) {
        float4 f0 = *(const float4*)&wv_g[tid * 8];
        float4 f1 = *(const float4*)&wv_g[tid * 8 + 4];
        __half2 h0 = __floats2half2_rn(f0.x, f0.y);
        __half2 h1 = __floats2half2_rn(f0.z, f0.w);
        __half2 h2 = __floats2half2_rn(f1.x, f1.y);
        __half2 h3 = __floats2half2_rn(f1.z, f1.w);
        uint4 u;
        u.x = *(unsigned*)&h0; u.y = *(unsigned*)&h1;
        u.z = *(unsigned*)&h2; u.w = *(unsigned*)&h3;
        sm->wvh[tid] = u;
    }

    const int qg   = w >> 1;
    const int rowk = (w & 1) * 32 + lane;
    const int q0   = qg * 2;

    int u = blockIdx.x;
    score_prefetch(sm, qp, kp, u, 0, tid);
    cp_commit();
    int p = 0;

    while (u < NUNITS) {
        int un = u + SGRID;
        if (un < NUNITS) {
            score_prefetch(sm, qp, kp, un, p ^ 1, tid);
            cp_commit();
            asm volatile("cp.async.wait_group 1;\n");
        } else {
            asm volatile("cp.async.wait_group 0;\n");
        }
        __syncthreads();

        const uint4* kb = sm->kbh[p];
        const uint4* qs = sm->qsh[p];
        float a00 = 0.f, a01 = 0.f, a10 = 0.f, a11 = 0.f;
#pragma unroll 4
        for (int h16 = 0; h16 < 16; h16++) {
            const int hA = 2 * h16, hB = 2 * h16 + 1;
            uint4 kuA = kb[rowk * 32 + (hA ^ lane)];
            uint4 kuB = kb[rowk * 32 + (hB ^ lane)];
            uint4 quA0 = qs[q0 * 32 + hA];
            uint4 quB0 = qs[q0 * 32 + hB];
            uint4 quA1 = qs[q0 * 32 + 32 + hA];
            uint4 quB1 = qs[q0 * 32 + 32 + hB];
            uint4 wuA = sm->wvh[hA];
            uint4 wuB = sm->wvh[hB];
            __half2 kA0 = u2h(kuA.x), kA1 = u2h(kuA.y), kA2 = u2h(kuA.z), kA3 = u2h(kuA.w);
            __half2 kB0 = u2h(kuB.x), kB1 = u2h(kuB.y), kB2 = u2h(kuB.z), kB3 = u2h(kuB.w);
            __half2 wA0 = u2h(wuA.x), wA1 = u2h(wuA.y), wA2 = u2h(wuA.z), wA3 = u2h(wuA.w);
            __half2 wB0 = u2h(wuB.x), wB1 = u2h(wuB.y), wB2 = u2h(wuB.z), wB3 = u2h(wuB.w);
            // query 0: 8-link fp16 chain
            __half2 s0;
            s0 = __hmul2(tanh2_ap(__hadd2(u2h(quA0.x), kA0)), wA0);
            s0 = __hfma2(tanh2_ap(__hadd2(u2h(quA0.y), kA1)), wA1, s0);
            s0 = __hfma2(tanh2_ap(__hadd2(u2h(quA0.z), kA2)), wA2, s0);
            s0 = __hfma2(tanh2_ap(__hadd2(u2h(quA0.w), kA3)), wA3, s0);
            s0 = __hfma2(tanh2_ap(__hadd2(u2h(quB0.x), kB0)), wB0, s0);
            s0 = __hfma2(tanh2_ap(__hadd2(u2h(quB0.y), kB1)), wB1, s0);
            s0 = __hfma2(tanh2_ap(__hadd2(u2h(quB0.z), kB2)), wB2, s0);
            s0 = __hfma2(tanh2_ap(__hadd2(u2h(quB0.w), kB3)), wB3, s0);
            float2 f0 = __half22float2(s0);
            a00 += f0.x; a01 += f0.y;
            // query 1
            __half2 s1;
            s1 = __hmul2(tanh2_ap(__hadd2(u2h(quA1.x), kA0)), wA0);
            s1 = __hfma2(tanh2_ap(__hadd2(u2h(quA1.y), kA1)), wA1, s1);
            s1 = __hfma2(tanh2_ap(__hadd2(u2h(quA1.z), kA2)), wA2, s1);
            s1 = __hfma2(tanh2_ap(__hadd2(u2h(quA1.w), kA3)), wA3, s1);
            s1 = __hfma2(tanh2_ap(__hadd2(u2h(quB1.x), kB0)), wB0, s1);
            s1 = __hfma2(tanh2_ap(__hadd2(u2h(quB1.y), kB1)), wB1, s1);
            s1 = __hfma2(tanh2_ap(__hadd2(u2h(quB1.z), kB2)), wB2, s1);
            s1 = __hfma2(tanh2_ap(__hadd2(u2h(quB1.w), kB3)), wB3, s1);
            float2 f1 = __half22float2(s1);
            a10 += f1.x; a11 += f1.y;
        }
        {
            const int qt = u >> 3;
            const int kt = u & 7;
            const int b = qt >> 6;
            const int qbase = (qt & 63) * 8;
            const int key = kt * 64 + rowk;
            scores[(size_t)(b * Qv + qbase + q0) * Kv + key]     = a00 + a01;
            scores[(size_t)(b * Qv + qbase + q0 + 1) * Kv + key] = a10 + a11;
        }
        __syncthreads();
        u = un; p ^= 1;
    }
}

// ---------------------------------------------------------------------------
// Softmax + PV. Grid 128: block = 16 queries, 512 threads (16 warps).
// Softmax: warp w -> query w. PV: warp w -> qgroup (w&3)*4..+4,
// dim quarter (w>>2)*64 (lane: 2 dims). V tiles (32 keys) double-buffered.
// smem: ps f32[16][512] 32KB | vb f32[2][32][256] 64KB = 96KB
// ---------------------------------------------------------------------------
__global__ __launch_bounds__(512) void softmax_pv_kernel(
    const float* __restrict__ scores, const float* __restrict__ V,
    float* __restrict__ out)
{
    extern __shared__ float smB[];
    float* ps = smB;               // [16][512]
    float* vb = smB + 16 * Kv;     // [2][32][256]

    const int tid  = threadIdx.x;
    const int lane = tid & 31;
    const int w    = tid >> 5;
    const int b     = blockIdx.x >> 5;
    const int qbase = (blockIdx.x & 31) * 16;

    const float4* vsrc_base = (const float4*)V + (size_t)(b * Kv) * 64;

    // prefetch V tile 0 (32 keys x 256 dims)
#pragma unroll
    for (int j = 0; j < 4; j++) {
        int idx = j * 512 + tid;
        int r = idx >> 6, c = idx & 63;
        cp_async16(&vb[r * Hv + c * 4], &vsrc_base[r * 64 + c]);
    }
    cp_commit();

    // ---- softmax: warp w handles query qbase+w ----
    {
        const float LOG2E = 1.4426950408889634f;
        const float* src = &scores[(size_t)(b * Qv + qbase + w) * Kv];
        float4 xv[4];
        float mx = -1e30f;
#pragma unroll
        for (int j = 0; j < 4; j++) {
            xv[j] = *(const float4*)&src[j * 128 + lane * 4];
            mx = fmaxf(mx, fmaxf(fmaxf(xv[j].x, xv[j].y), fmaxf(xv[j].z, xv[j].w)));
        }
#pragma unroll
        for (int off = 16; off > 0; off >>= 1)
            mx = fmaxf(mx, __shfl_xor_sync(0xffffffffu, mx, off));
        float s = 0.f;
#pragma unroll
        for (int j = 0; j < 4; j++) {
            xv[j].x = ex2_ap((xv[j].x - mx) * LOG2E);
            xv[j].y = ex2_ap((xv[j].y - mx) * LOG2E);
            xv[j].z = ex2_ap((xv[j].z - mx) * LOG2E);
            xv[j].w = ex2_ap((xv[j].w - mx) * LOG2E);
            s += xv[j].x + xv[j].y + xv[j].z + xv[j].w;
        }
#pragma unroll
        for (int off = 16; off > 0; off >>= 1)
            s += __shfl_xor_sync(0xffffffffu, s, off);
        float inv = __fdividef(1.f, s);
#pragma unroll
        for (int j = 0; j < 4; j++) {
            xv[j].x *= inv; xv[j].y *= inv; xv[j].z *= inv; xv[j].w *= inv;
            *(float4*)&ps[w * Kv + j * 128 + lane * 4] = xv[j];
        }
    }

    // ---- PV ----
    const int qg  = w & 3;
    const int dof = (w >> 2) * 64 + lane * 2;

    float2 acc[4];
#pragma unroll
    for (int j = 0; j < 4; j++) acc[j] = make_float2(0.f, 0.f);

    for (int kt = 0; kt < 16; kt++) {
        if (kt < 15) {
            float* dst = vb + ((kt + 1) & 1) * 32 * Hv;
            const float4* src = vsrc_base + (size_t)(kt + 1) * 32 * 64;
#pragma unroll
            for (int j = 0; j < 4; j++) {
                int idx = j * 512 + tid;
                int r = idx >> 6, c = idx & 63;
                cp_async16(&dst[r * Hv + c * 4], &src[r * 64 + c]);
            }
            cp_commit();
            asm volatile("cp.async.wait_group 1;\n");
        } else {
            asm volatile("cp.async.wait_group 0;\n");
        }
        __syncthreads();

        const float* vt = vb + (kt & 1) * 32 * Hv;
#pragma unroll 2
        for (int kk4 = 0; kk4 < 8; kk4++) {
            float p[4][4];
#pragma unroll
            for (int j = 0; j < 4; j++) {
                float4 p4 = *(const float4*)&ps[(qg * 4 + j) * Kv + kt * 32 + kk4 * 4];
                p[j][0] = p4.x; p[j][1] = p4.y; p[j][2] = p4.z; p[j][3] = p4.w;
            }
#pragma unroll
            for (int kk = 0; kk < 4; kk++) {
                float2 v = *(const float2*)&vt[(kk4 * 4 + kk) * Hv + dof];
#pragma unroll
                for (int j = 0; j < 4; j++) {
                    acc[j].x = fmaf(p[j][kk], v.x, acc[j].x);
                    acc[j].y = fmaf(p[j][kk], v.y, acc[j].y);
                }
            }
        }
        __syncthreads();
    }
#pragma unroll
    for (int j = 0; j < 4; j++) {
        *(float2*)&out[(size_t)(b * Qv + qbase + qg * 4 + j) * Hv + dof] = acc[j];
    }
}

extern "C" void kernel_launch(void* const* d_in, const int* in_sizes, int n_in,
                              void* d_out, int out_size)
{
    const float* queries = (const float*)d_in[0];
    const float* keys    = (const float*)d_in[1];
    const float* values  = (const float*)d_in[2];
    const float* W_q     = (const float*)d_in[3];
    const float* W_k     = (const float*)d_in[4];
    const float* w_v     = (const float*)d_in[5];
    float* out = (float*)d_out;

    uint4 *qph, *kph; float* sc;
    cudaGetSymbolAddress((void**)&qph, g_qph);
    cudaGetSymbolAddress((void**)&kph, g_kph);
    cudaGetSymbolAddress((void**)&sc, g_sc);

    proj_kernel<<<dim3(4, 32, 2), 256>>>(queries, W_q, (__half*)qph,
                                         keys, W_k, (__half*)kph);

    const int smA = (int)sizeof(ScoreSmem);   // 512 + 8192 + 65536 = 74240 B
    cudaFuncSetAttribute(score_kernel, cudaFuncAttributeMaxDynamicSharedMemorySize, smA);
    score_kernel<<<SGRID, 256, smA>>>(qph, kph, w_v, sc);

    const int smB = (16 * Kv + 2 * 32 * Hv) * (int)sizeof(float);  // 98304 B
    cudaFuncSetAttribute(softmax_pv_kernel, cudaFuncAttributeMaxDynamicSharedMemorySize, smB);
    softmax_pv_kernel<<<128, 512, smB>>>(sc, values, out);
}